// round 12
// baseline (speedup 1.0000x reference)
#include <cuda_runtime.h>
#include <cstdint>

#define TPB 256

__device__ __forceinline__ float4 ldcs4(const float4* p) { return __ldcs(p); }
__device__ __forceinline__ void stcs4(float4* p, float4 v) { __stcs(p, v); }

__global__ __launch_bounds__(TPB, 6) void tp_kernel(
    const float* __restrict__ x0, const float* __restrict__ y0,
    const float* __restrict__ x1, const float* __restrict__ y1,
    const float* __restrict__ x2, const float* __restrict__ y2,
    float* __restrict__ out, long long NC)
{
    __shared__ float sA[TPB * 9];
    __shared__ float sB[TPB * 9];
    __shared__ float su[TPB * 3];
    __shared__ float sv[TPB * 3];
    __shared__ float sa[TPB];
    __shared__ float sb[TPB];

    const long long base = (long long)blockIdx.x * TPB;
    const int t = threadIdx.x;
    long long rem = NC - base;
    const int npair = rem < TPB ? (int)rem : TPB;
    const bool full = (npair == TPB);

    if (full) {
        // ---- Load-balanced front-batched staging.
        //      1664 float4 per block spread 6-7 per thread (max live payload
        //      28 regs instead of 40). All masks are warp-uniform (64-bounds):
        //        every thread : A[t], A[t+256], B[t], B[t+256]   (4 loads)
        //        t <  192     : u[t]                             (+1)
        //        t >=  64     : v[t-64]                          (+1)
        //        quadrant     : one of A3 / B3 / a / b           (+1)
        const float4* gA = (const float4*)(x2 + base * 9);   // 576 float4
        const float4* gB = (const float4*)(y2 + base * 9);   // 576 float4
        const float4* gu = (const float4*)(x1 + base * 3);   // 192 float4
        const float4* gv = (const float4*)(y1 + base * 3);   // 192 float4
        const float4* ga = (const float4*)(x0 + base);       //  64 float4
        const float4* gb = (const float4*)(y0 + base);       //  64 float4

        const bool mu = (t < 192);
        const bool mv = (t >= 64);
        const int  q  = t >> 6;          // quadrant 0..3 (warp-uniform)

        float4 rA0 = ldcs4(gA + t);
        float4 rB0 = ldcs4(gB + t);
        float4 rA1 = ldcs4(gA + t + 256);
        float4 rB1 = ldcs4(gB + t + 256);
        float4 ru, rv, rex;
        if (mu) ru = ldcs4(gu + t);
        if (mv) rv = ldcs4(gv + (t - 64));
        if      (q == 0) rex = ldcs4(gA + t + 512);          // A3[0..63]
        else if (q == 1) rex = ldcs4(gB + (t - 64) + 512);   // B3[0..63]
        else if (q == 2) rex = ldcs4(ga + (t - 128));        // a[0..63]
        else             rex = ldcs4(gb + (t - 192));        // b[0..63]

        float4* s4A = (float4*)sA;
        float4* s4B = (float4*)sB;
        float4* s4u = (float4*)su;
        float4* s4v = (float4*)sv;
        float4* s4a = (float4*)sa;
        float4* s4b = (float4*)sb;
        s4A[t]       = rA0;
        s4B[t]       = rB0;
        s4A[t + 256] = rA1;
        s4B[t + 256] = rB1;
        if (mu) s4u[t] = ru;
        if (mv) s4v[t - 64] = rv;
        if      (q == 0) s4A[t + 512]        = rex;
        else if (q == 1) s4B[(t - 64) + 512] = rex;
        else if (q == 2) s4a[t - 128]        = rex;
        else             s4b[t - 192]        = rex;
    } else {
        for (int i = t; i < npair * 9; i += TPB) { sA[i] = x2[base * 9 + i]; sB[i] = y2[base * 9 + i]; }
        for (int i = t; i < npair * 3; i += TPB) { su[i] = x1[base * 3 + i]; sv[i] = y1[base * 3 + i]; }
        for (int i = t; i < npair;     i += TPB) { sa[i] = x0[base + i];     sb[i] = y0[base + i]; }
    }
    __syncthreads();

    // ---- Per-pair compute. Operands pulled fully into registers, results
    //      written straight back into this thread's OWN smem slots (slot t is
    //      touched only by thread t between the two barriers). ----
    if (t < npair) {
        const float a = sa[t], b = sb[t];
        float u[3], v[3], A[9], B[9];
        #pragma unroll
        for (int i = 0; i < 3; i++) { u[i] = su[t * 3 + i]; v[i] = sv[t * 3 + i]; }
        #pragma unroll
        for (int i = 0; i < 9; i++) { A[i] = sA[t * 9 + i]; B[i] = sB[t * 9 + i]; }

        // z2 = a*B + b*A + u (x) v + A@B  -> sA[t*9+..]
        #pragma unroll
        for (int i = 0; i < 3; i++) {
            #pragma unroll
            for (int j = 0; j < 3; j++) {
                float s = fmaf(a, B[i * 3 + j], b * A[i * 3 + j]);
                s = fmaf(u[i], v[j], s);
                #pragma unroll
                for (int k = 0; k < 3; k++)
                    s = fmaf(A[i * 3 + k], B[k * 3 + j], s);
                sA[t * 9 + i * 3 + j] = s;
            }
        }
        // z1 = a*v + b*u + u.B + A.v  -> su[t*3+..]
        #pragma unroll
        for (int i = 0; i < 3; i++) {
            float s = fmaf(a, v[i], b * u[i]);
            #pragma unroll
            for (int d = 0; d < 3; d++) {
                s = fmaf(u[d], B[d * 3 + i], s);
                s = fmaf(A[i * 3 + d], v[d], s);
            }
            su[t * 3 + i] = s;
        }
        // z0 = a*b + u.v + <A,B>  -> sa[t]
        float z0 = a * b;
        #pragma unroll
        for (int i = 0; i < 3; i++) z0 = fmaf(u[i], v[i], z0);
        #pragma unroll
        for (int i = 0; i < 9; i++) z0 = fmaf(A[i], B[i], z0);
        sa[t] = z0;
    }
    __syncthreads();

    // ---- Coalesced streaming stores ----
    float* o0 = out;
    float* o1 = out + NC;
    float* o2 = out + 4 * NC;
    if (full) {
        float4* g0 = (float4*)(o0 + base);
        float4* g1 = (float4*)(o1 + base * 3);
        float4* g2 = (float4*)(o2 + base * 9);
        const float4* s40 = (const float4*)sa;
        const float4* s41 = (const float4*)su;
        const float4* s42 = (const float4*)sA;
        stcs4(g2 + t,       s42[t]);
        stcs4(g2 + t + 256, s42[t + 256]);
        if (t < 192) stcs4(g1 + t, s41[t]);
        if (t >= 64 && t < 128) stcs4(g2 + (t - 64) + 512, s42[(t - 64) + 512]);
        if (t >= 128 && t < 192) stcs4(g0 + (t - 128), s40[t - 128]);
    } else {
        for (int i = t; i < npair;     i += TPB) o0[base + i]     = sa[i];
        for (int i = t; i < npair * 3; i += TPB) o1[base * 3 + i] = su[i];
        for (int i = t; i < npair * 9; i += TPB) o2[base * 9 + i] = sA[i];
    }
}

extern "C" void kernel_launch(void* const* d_in, const int* in_sizes, int n_in,
                              void* d_out, int out_size)
{
    // out = (z0, z1, z2) concatenated: 13*NC floats
    const long long NC = (long long)out_size / 13;

    // Classify inputs by element count; x precedes y within each size class
    // in both plausible metadata orderings.
    const float *x0 = nullptr, *y0 = nullptr, *x1 = nullptr, *y1 = nullptr,
                *x2 = nullptr, *y2 = nullptr;
    for (int i = 0; i < n_in; i++) {
        long long s = in_sizes[i];
        const float* p = (const float*)d_in[i];
        if (s == NC)          { if (!x0) x0 = p; else y0 = p; }
        else if (s == 3 * NC) { if (!x1) x1 = p; else y1 = p; }
        else if (s == 9 * NC) { if (!x2) x2 = p; else y2 = p; }
    }

    const int nblocks = (int)((NC + TPB - 1) / TPB);
    tp_kernel<<<nblocks, TPB>>>(x0, y0, x1, y1, x2, y2, (float*)d_out, NC);
}